// round 8
// baseline (speedup 1.0000x reference)
#include <cuda_runtime.h>
#include <cuda_bf16.h>

#define NN 50000
#define EE 1600000
#define GG 512
#define FIN 9
#define HH 64
#define NBLK_SCAN ((NN + 1023) / 1024)   // 49
#define FULL 0xffffffffu

// ---------------- constant weights (copied in at launch, D2D async) ----------------
#define OFF_W1A 0          // 64x9   = 576
#define OFF_W1B 576        // 64x64  = 4096
#define OFF_W2A 4672       // 64x64  = 4096
#define OFF_W2B 8768       // 64x64  = 4096
#define OFF_WR1 12864      // 32x64  = 2048
__constant__ float c_w[14912];

// ---------------- scratch (static device memory; no allocations) ----------------
__device__ int   g_deg [NN];
__device__ int   g_off [NN];
__device__ int   g_cur [NN];
__device__ int   g_bsum[NBLK_SCAN];
__device__ __align__(16) int2  g_csr[EE];          // packed {src, ea bits}
__device__ __align__(16) float g_agg1[NN * FIN];
__device__ __align__(16) float g_h1  [NN * HH];
__device__ __align__(16) float g_agg2[NN * HH];
__device__ float g_pi [NN];
__device__ float g_tot[GG];

// ---------------- f32x2 helpers ----------------
__device__ __forceinline__ unsigned long long pk2(float a, float b) {
    unsigned long long r;
    asm("mov.b64 %0,{%1,%2};" : "=l"(r) : "f"(a), "f"(b));
    return r;
}
__device__ __forceinline__ void upk2(unsigned long long v, float& a, float& b) {
    asm("mov.b64 {%0,%1},%2;" : "=f"(a), "=f"(b) : "l"(v));
}
__device__ __forceinline__ unsigned long long ffma2(unsigned long long a,
                                                    unsigned long long b,
                                                    unsigned long long c) {
    unsigned long long d;
    asm("fma.rn.f32x2 %0,%1,%2,%3;" : "=l"(d) : "l"(a), "l"(b), "l"(c));
    return d;
}

// ---------------- init ----------------
__global__ void k_init() {
    int i = blockIdx.x * blockDim.x + threadIdx.x;
    if (i < NN) g_deg[i] = 0;
    if (i < GG) g_tot[i] = 0.0f;
}

// ---------------- histogram of dst ----------------
__global__ void k_hist(const int* __restrict__ ei) {
    int e = blockIdx.x * blockDim.x + threadIdx.x;
    if (e >= EE) return;
    atomicAdd(&g_deg[ei[EE + e]], 1);
}

// ---------------- scan phase 1 ----------------
__global__ void k_scan1() {
    __shared__ int wsum[32];
    int tid = threadIdx.x, lane = tid & 31, wid = tid >> 5;
    int i = blockIdx.x * 1024 + tid;
    int v = (i < NN) ? g_deg[i] : 0;
    int x = v;
#pragma unroll
    for (int o = 1; o < 32; o <<= 1) {
        int y = __shfl_up_sync(FULL, x, o);
        if (lane >= o) x += y;
    }
    if (lane == 31) wsum[wid] = x;
    __syncthreads();
    if (wid == 0) {
        int w = wsum[lane];
#pragma unroll
        for (int o = 1; o < 32; o <<= 1) {
            int y = __shfl_up_sync(FULL, w, o);
            if (lane >= o) w += y;
        }
        wsum[lane] = w;
    }
    __syncthreads();
    int wp = (wid == 0) ? 0 : wsum[wid - 1];
    if (i < NN) g_off[i] = wp + x - v;
    if (tid == 1023) g_bsum[blockIdx.x] = wsum[31];
}

// ---------------- scan phases 2+3 ----------------
__global__ void k_scan23() {
    __shared__ int sb[64];
    int tid = threadIdx.x;
    if (tid < 64) sb[tid] = (tid < NBLK_SCAN) ? g_bsum[tid] : 0;
    __syncthreads();
    if (tid == 0) {
        int run = 0;
        for (int j = 0; j < NBLK_SCAN; j++) { int t = sb[j]; sb[j] = run; run += t; }
    }
    __syncthreads();
    int i = blockIdx.x * blockDim.x + tid;
    if (i < NN) {
        int v = g_off[i] + sb[i >> 10];
        g_off[i] = v;
        g_cur[i] = v;
    }
}

// ---------------- scatter edges into packed CSR ----------------
__global__ void k_scatter(const int* __restrict__ ei,
                          const float* __restrict__ ea) {
    int e = blockIdx.x * blockDim.x + threadIdx.x;
    if (e >= EE) return;
    int s = ei[e];
    int d = ei[EE + e];
    int p = atomicAdd(&g_cur[d], 1);
    g_csr[p] = make_int2(s, __float_as_int(ea[e]));
}

// ================= gather1: warp-per-node, 3 edges/step (F=9) =================
__global__ void __launch_bounds__(256) k_gather1(const float* __restrict__ x,
                        const float* __restrict__ e1w, const float* __restrict__ e1b) {
    __shared__ int2 s_edge[8][32];
    int lane = threadIdx.x & 31, w = threadIdx.x >> 5;
    int n = blockIdx.x * 8 + w;
    if (n >= NN) return;

    int eoff = lane / FIN;
    int f = lane - eoff * FIN;
    bool act = (lane < 27);
    float wv = act ? e1w[f] : 0.0f;
    float bv = act ? e1b[f] : 0.0f;

    int base = g_off[n], deg = g_deg[n];
    float acc = 0.0f;
    for (int c = 0; c < deg; c += 32) {
        int cnt = min(deg - c, 32);
        if (lane < cnt) s_edge[w][lane] = g_csr[base + c + lane];
        __syncwarp();
        if (cnt == 32) {
#pragma unroll
            for (int t = 0; t < 11; t++) {
                int idx = 3 * t + eoff;
                if (act && idx < 32) {
                    int2 e = s_edge[w][idx];
                    float a = __int_as_float(e.y);
                    float xv = x[e.x * FIN + f];
                    acc += fmaxf(xv + a * wv + bv, 0.0f);
                }
            }
        } else {
            int steps = (cnt + 2) / 3;
            for (int t = 0; t < steps; t++) {
                int idx = 3 * t + eoff;
                if (act && idx < cnt) {
                    int2 e = s_edge[w][idx];
                    float a = __int_as_float(e.y);
                    float xv = x[e.x * FIN + f];
                    acc += fmaxf(xv + a * wv + bv, 0.0f);
                }
            }
        }
        __syncwarp();
    }
    float v1 = __shfl_down_sync(FULL, acc, 9);
    float v2 = __shfl_down_sync(FULL, acc, 18);
    if (lane < FIN) g_agg1[n * FIN + lane] = x[n * FIN + lane] + acc + v1 + v2;
}

// ================= mlp1: lane=node, weights in constant, f32x2 =================
__global__ void __launch_bounds__(128, 2) k_mlp1(const float* __restrict__ b1a,
                                                 const float* __restrict__ b1b) {
    __shared__ __align__(16) float s[4][32 * 66];
    __shared__ float sba[HH], sbb[HH];
    int tid = threadIdx.x, lane = tid & 31, w = tid >> 5;
    if (tid < HH) { sba[tid] = b1a[tid]; sbb[tid] = b1b[tid]; }
    __syncthreads();

    int nbase = (blockIdx.x * 4 + w) * 32;

    // stage agg1 (32 nodes x 9) into padded shared, transposed access
    for (int r = 0; r < 9; r++) {
        int idx = r * 32 + lane;
        int gidx = nbase * FIN + idx;
        float v = (gidx < NN * FIN) ? g_agg1[gidx] : 0.0f;
        int node = idx / FIN, feat = idx - node * FIN;
        s[w][node * 66 + feat] = v;
    }
    __syncwarp();

    float a1[FIN];
#pragma unroll
    for (int k = 0; k < FIN; k++) a1[k] = s[w][lane * 66 + k];

    // stage1: 9 -> 64 (scalar fma), results packed into pairs
    unsigned long long p1[32];
    float t0 = 0.0f;
#pragma unroll 8
    for (int j = 0; j < HH; j++) {
        float acc = sba[j];
#pragma unroll
        for (int k = 0; k < FIN; k++) acc = fmaf(a1[k], c_w[OFF_W1A + j * FIN + k], acc);
        acc = fmaxf(acc, 0.0f);
        if (j & 1) p1[j >> 1] = pk2(t0, acc); else t0 = acc;
    }

    // stage2: 64 -> 64 with f32x2
    const unsigned long long* cw = (const unsigned long long*)(c_w + OFF_W1B);
#pragma unroll 4
    for (int j = 0; j < HH; j++) {
        unsigned long long acc2 = pk2(sbb[j], 0.0f);
#pragma unroll
        for (int q = 0; q < 32; q++) acc2 = ffma2(p1[q], cw[j * 32 + q], acc2);
        float lo, hi; upk2(acc2, lo, hi);
        s[w][lane * 66 + j] = fmaxf(lo + hi, 0.0f);
    }
    __syncwarp();

    // coalesced transpose write of h1
    for (int r = 0; r < 64; r++) {
        int idx = r * 32 + lane;
        int gidx = nbase * HH + idx;
        if (gidx < NN * HH) g_h1[gidx] = s[w][(r >> 1) * 66 + (r & 1) * 32 + lane];
    }
}

// ================= gather2: warp-per-node (F=64), batched loads =================
__global__ void __launch_bounds__(256) k_gather2(const float* __restrict__ e2w,
                                                 const float* __restrict__ e2b) {
    __shared__ int2 s_edge[8][32];
    int lane = threadIdx.x & 31, w = threadIdx.x >> 5;
    int n = blockIdx.x * 8 + w;
    if (n >= NN) return;

    float2 wv = ((const float2*)e2w)[lane];
    float2 bv = ((const float2*)e2b)[lane];
    const float2* h1f2 = (const float2*)g_h1;

    int base = g_off[n], deg = g_deg[n];
    float2 acc = h1f2[n * 32 + lane];
    for (int c = 0; c < deg; c += 32) {
        int cnt = min(deg - c, 32);
        if (lane < cnt) s_edge[w][lane] = g_csr[base + c + lane];
        __syncwarp();
        if (cnt == 32) {
#pragma unroll
            for (int kb = 0; kb < 4; kb++) {
                float2 h[8]; float a[8];
#pragma unroll
                for (int u = 0; u < 8; u++) {
                    int2 e = s_edge[w][kb * 8 + u];
                    a[u] = __int_as_float(e.y);
                    h[u] = h1f2[e.x * 32 + lane];
                }
#pragma unroll
                for (int u = 0; u < 8; u++) {
                    acc.x += fmaxf(h[u].x + a[u] * wv.x + bv.x, 0.0f);
                    acc.y += fmaxf(h[u].y + a[u] * wv.y + bv.y, 0.0f);
                }
            }
        } else {
            for (int k = 0; k < cnt; k++) {
                int2 e = s_edge[w][k];
                float a = __int_as_float(e.y);
                float2 h = h1f2[e.x * 32 + lane];
                acc.x += fmaxf(h.x + a * wv.x + bv.x, 0.0f);
                acc.y += fmaxf(h.y + a * wv.y + bv.y, 0.0f);
            }
        }
        __syncwarp();
    }
    ((float2*)g_agg2)[n * 32 + lane] = acc;
}

// ================= mlp2 + readout fused: lane=node, constant weights, f32x2 =================
__global__ void __launch_bounds__(128, 2) k_mlp2ro(const float* __restrict__ b2a,
                        const float* __restrict__ b2b,
                        const float* __restrict__ br1, const float* __restrict__ wr2,
                        const float* __restrict__ br2,
                        const int* __restrict__ batch,
                        const int* __restrict__ tmask,
                        const float* __restrict__ ccost) {
    __shared__ __align__(16) float s[4][32 * 66];
    __shared__ float sba[HH], sbb[HH], sbr[32], sw2[32];
    int tid = threadIdx.x, lane = tid & 31, w = tid >> 5;
    if (tid < HH) { sba[tid] = b2a[tid]; sbb[tid] = b2b[tid]; }
    if (tid < 32) { sbr[tid] = br1[tid]; sw2[tid] = wr2[tid]; }
    __syncthreads();

    int nbase = (blockIdx.x * 4 + w) * 32;

    // stage agg2 (32 nodes x 64) into padded shared (transposed)
    for (int r = 0; r < 64; r++) {
        int idx = r * 32 + lane;
        int gidx = nbase * HH + idx;
        s[w][(r >> 1) * 66 + (r & 1) * 32 + lane] = (gidx < NN * HH) ? g_agg2[gidx] : 0.0f;
    }
    __syncwarp();

    unsigned long long p0[32], p1[32], p2[32];
#pragma unroll
    for (int q = 0; q < 32; q++)
        p0[q] = *(const unsigned long long*)&s[w][lane * 66 + 2 * q];

    const unsigned long long* cwa = (const unsigned long long*)(c_w + OFF_W2A);
    const unsigned long long* cwb = (const unsigned long long*)(c_w + OFF_W2B);
    const unsigned long long* cwr = (const unsigned long long*)(c_w + OFF_WR1);

    // layer A: 64 -> 64
    float t0 = 0.0f;
#pragma unroll 4
    for (int j = 0; j < HH; j++) {
        unsigned long long acc2 = pk2(sba[j], 0.0f);
#pragma unroll
        for (int q = 0; q < 32; q++) acc2 = ffma2(p0[q], cwa[j * 32 + q], acc2);
        float lo, hi; upk2(acc2, lo, hi);
        float v = fmaxf(lo + hi, 0.0f);
        if (j & 1) p1[j >> 1] = pk2(t0, v); else t0 = v;
    }

    // layer B: 64 -> 64
#pragma unroll 4
    for (int j = 0; j < HH; j++) {
        unsigned long long acc2 = pk2(sbb[j], 0.0f);
#pragma unroll
        for (int q = 0; q < 32; q++) acc2 = ffma2(p1[q], cwb[j * 32 + q], acc2);
        float lo, hi; upk2(acc2, lo, hi);
        float v = fmaxf(lo + hi, 0.0f);
        if (j & 1) p2[j >> 1] = pk2(t0, v); else t0 = v;
    }

    // readout: 64 -> 32 -> 1
    float z = 0.0f;
#pragma unroll 4
    for (int j = 0; j < 32; j++) {
        unsigned long long acc2 = pk2(sbr[j], 0.0f);
#pragma unroll
        for (int q = 0; q < 32; q++) acc2 = ffma2(p2[q], cwr[j * 32 + q], acc2);
        float lo, hi; upk2(acc2, lo, hi);
        z = fmaf(fmaxf(lo + hi, 0.0f), sw2[j], z);
    }

    int n = nbase + lane;
    if (n < NN) {
        z += br2[0];
        float pi = 1.0f / (1.0f + __expf(-z));
        pi *= (1.0f - (float)tmask[n]);
        g_pi[n] = pi;
        atomicAdd(&g_tot[batch[n]], pi * ccost[n]);
    }
}

// ---------------- final ----------------
__global__ void k_final(const int* __restrict__ batch,
                        const float* __restrict__ Bt,
                        float* __restrict__ out) {
    int i = blockIdx.x * blockDim.x + threadIdx.x;
    if (i >= NN) return;
    int b = batch[i];
    float ratio = fminf(Bt[b] / (g_tot[b] + 1e-12f), 1.0f);
    out[i] = g_pi[i] * ratio;
}

extern "C" void kernel_launch(void* const* d_in, const int* in_sizes, int n_in,
                              void* d_out, int out_size) {
    const float* x      = (const float*)d_in[0];
    const int*   ei     = (const int*)d_in[1];
    const float* ea     = (const float*)d_in[2];
    const int*   batch  = (const int*)d_in[3];
    const float* Btot   = (const float*)d_in[4];
    const int*   tmask  = (const int*)d_in[5];
    const float* ccost  = (const float*)d_in[6];
    const float* e1w    = (const float*)d_in[7];
    const float* e1b    = (const float*)d_in[8];
    const float* w1a    = (const float*)d_in[9];
    const float* b1a    = (const float*)d_in[10];
    const float* w1b    = (const float*)d_in[11];
    const float* b1b    = (const float*)d_in[12];
    const float* e2w    = (const float*)d_in[13];
    const float* e2b    = (const float*)d_in[14];
    const float* w2a    = (const float*)d_in[15];
    const float* b2a    = (const float*)d_in[16];
    const float* w2b    = (const float*)d_in[17];
    const float* b2b    = (const float*)d_in[18];
    const float* wr1    = (const float*)d_in[19];
    const float* br1    = (const float*)d_in[20];
    const float* wr2    = (const float*)d_in[21];
    const float* br2    = (const float*)d_in[22];
    float* out = (float*)d_out;

    // weights -> constant memory (async D2D, graph-capturable)
    cudaMemcpyToSymbolAsync(c_w, w1a, 576 * 4,  OFF_W1A * 4, cudaMemcpyDeviceToDevice, 0);
    cudaMemcpyToSymbolAsync(c_w, w1b, 4096 * 4, OFF_W1B * 4, cudaMemcpyDeviceToDevice, 0);
    cudaMemcpyToSymbolAsync(c_w, w2a, 4096 * 4, OFF_W2A * 4, cudaMemcpyDeviceToDevice, 0);
    cudaMemcpyToSymbolAsync(c_w, w2b, 4096 * 4, OFF_W2B * 4, cudaMemcpyDeviceToDevice, 0);
    cudaMemcpyToSymbolAsync(c_w, wr1, 2048 * 4, OFF_WR1 * 4, cudaMemcpyDeviceToDevice, 0);

    k_init<<<(NN + 255) / 256, 256>>>();
    k_hist<<<(EE + 255) / 256, 256>>>(ei);
    k_scan1<<<NBLK_SCAN, 1024>>>();
    k_scan23<<<(NN + 255) / 256, 256>>>();
    k_scatter<<<(EE + 255) / 256, 256>>>(ei, ea);
    k_gather1<<<(NN + 7) / 8, 256>>>(x, e1w, e1b);
    k_mlp1<<<(NN + 127) / 128, 128>>>(b1a, b1b);
    k_gather2<<<(NN + 7) / 8, 256>>>(e2w, e2b);
    k_mlp2ro<<<(NN + 127) / 128, 128>>>(b2a, b2b, br1, wr2, br2, batch, tmask, ccost);
    k_final<<<(NN + 255) / 256, 256>>>(batch, Btot, out);
}

// round 9
// speedup vs baseline: 1.3052x; 1.3052x over previous
#include <cuda_runtime.h>
#include <cuda_bf16.h>

#define NN 50000
#define EE 1600000
#define GG 512
#define FIN 9
#define HH 64
#define NBLK_SCAN ((NN + 1023) / 1024)   // 49
#define FULL 0xffffffffu

// ---------------- scratch (static device memory; no allocations) ----------------
__device__ int   g_deg [NN];
__device__ int   g_off [NN];
__device__ int   g_cur [NN];
__device__ int   g_bsum[NBLK_SCAN];
__device__ __align__(16) int2  g_csr[EE];          // packed {src, ea bits}
__device__ __align__(16) float g_agg1[NN * FIN];
__device__ __align__(16) float g_h1  [NN * HH];
__device__ __align__(16) float g_agg2[NN * HH];
__device__ float g_pi [NN];
__device__ float g_tot[GG];

// ---------------- f32x2 helpers ----------------
__device__ __forceinline__ unsigned long long pk2(float a, float b) {
    unsigned long long r;
    asm("mov.b64 %0,{%1,%2};" : "=l"(r) : "f"(a), "f"(b));
    return r;
}
__device__ __forceinline__ void upk2(unsigned long long v, float& a, float& b) {
    asm("mov.b64 {%0,%1},%2;" : "=f"(a), "=f"(b) : "l"(v));
}
__device__ __forceinline__ unsigned long long ffma2(unsigned long long a,
                                                    unsigned long long b,
                                                    unsigned long long c) {
    unsigned long long d;
    asm("fma.rn.f32x2 %0,%1,%2,%3;" : "=l"(d) : "l"(a), "l"(b), "l"(c));
    return d;
}

// ---------------- init ----------------
__global__ void k_init() {
    int i = blockIdx.x * blockDim.x + threadIdx.x;
    if (i < NN) g_deg[i] = 0;
    if (i < GG) g_tot[i] = 0.0f;
}

// ---------------- histogram of dst ----------------
__global__ void k_hist(const int* __restrict__ ei) {
    int e = blockIdx.x * blockDim.x + threadIdx.x;
    if (e >= EE) return;
    atomicAdd(&g_deg[ei[EE + e]], 1);
}

// ---------------- scan phase 1 ----------------
__global__ void k_scan1() {
    __shared__ int wsum[32];
    int tid = threadIdx.x, lane = tid & 31, wid = tid >> 5;
    int i = blockIdx.x * 1024 + tid;
    int v = (i < NN) ? g_deg[i] : 0;
    int x = v;
#pragma unroll
    for (int o = 1; o < 32; o <<= 1) {
        int y = __shfl_up_sync(FULL, x, o);
        if (lane >= o) x += y;
    }
    if (lane == 31) wsum[wid] = x;
    __syncthreads();
    if (wid == 0) {
        int w = wsum[lane];
#pragma unroll
        for (int o = 1; o < 32; o <<= 1) {
            int y = __shfl_up_sync(FULL, w, o);
            if (lane >= o) w += y;
        }
        wsum[lane] = w;
    }
    __syncthreads();
    int wp = (wid == 0) ? 0 : wsum[wid - 1];
    if (i < NN) g_off[i] = wp + x - v;
    if (tid == 1023) g_bsum[blockIdx.x] = wsum[31];
}

// ---------------- scan phases 2+3 ----------------
__global__ void k_scan23() {
    __shared__ int sb[64];
    int tid = threadIdx.x;
    if (tid < 64) sb[tid] = (tid < NBLK_SCAN) ? g_bsum[tid] : 0;
    __syncthreads();
    if (tid == 0) {
        int run = 0;
        for (int j = 0; j < NBLK_SCAN; j++) { int t = sb[j]; sb[j] = run; run += t; }
    }
    __syncthreads();
    int i = blockIdx.x * blockDim.x + tid;
    if (i < NN) {
        int v = g_off[i] + sb[i >> 10];
        g_off[i] = v;
        g_cur[i] = v;
    }
}

// ---------------- scatter edges into packed CSR ----------------
__global__ void k_scatter(const int* __restrict__ ei,
                          const float* __restrict__ ea) {
    int e = blockIdx.x * blockDim.x + threadIdx.x;
    if (e >= EE) return;
    int s = ei[e];
    int d = ei[EE + e];
    int p = atomicAdd(&g_cur[d], 1);
    g_csr[p] = make_int2(s, __float_as_int(ea[e]));
}

// ================= gather1: warp-per-node, 3 edges/step (F=9) =================
__global__ void __launch_bounds__(256) k_gather1(const float* __restrict__ x,
                        const float* __restrict__ e1w, const float* __restrict__ e1b) {
    __shared__ int2 s_edge[8][32];
    int lane = threadIdx.x & 31, w = threadIdx.x >> 5;
    int n = blockIdx.x * 8 + w;
    if (n >= NN) return;

    int eoff = lane / FIN;
    int f = lane - eoff * FIN;
    bool act = (lane < 27);
    float wv = act ? e1w[f] : 0.0f;
    float bv = act ? e1b[f] : 0.0f;

    int base = g_off[n], deg = g_deg[n];
    float acc = 0.0f;
    for (int c = 0; c < deg; c += 32) {
        int cnt = min(deg - c, 32);
        if (lane < cnt) s_edge[w][lane] = g_csr[base + c + lane];
        __syncwarp();
        if (cnt == 32) {
#pragma unroll
            for (int t = 0; t < 11; t++) {
                int idx = 3 * t + eoff;
                if (act && idx < 32) {
                    int2 e = s_edge[w][idx];
                    float a = __int_as_float(e.y);
                    float xv = x[e.x * FIN + f];
                    acc += fmaxf(xv + a * wv + bv, 0.0f);
                }
            }
        } else {
            int steps = (cnt + 2) / 3;
            for (int t = 0; t < steps; t++) {
                int idx = 3 * t + eoff;
                if (act && idx < cnt) {
                    int2 e = s_edge[w][idx];
                    float a = __int_as_float(e.y);
                    float xv = x[e.x * FIN + f];
                    acc += fmaxf(xv + a * wv + bv, 0.0f);
                }
            }
        }
        __syncwarp();
    }
    float v1 = __shfl_down_sync(FULL, acc, 9);
    float v2 = __shfl_down_sync(FULL, acc, 18);
    if (lane < FIN) g_agg1[n * FIN + lane] = x[n * FIN + lane] + acc + v1 + v2;
}

// ================= mlp1: lane=node, warp-uniform shared weights, f32x2 =================
// dynamic smem: sw1a[576] | sw1b[4096] | sba[64] | sbb[64] | stage[4][2112]
#define MLP1_SMEM ((576 + 4096 + 64 + 64 + 4 * 2112) * 4)
__global__ void __launch_bounds__(128, 2) k_mlp1(const float* __restrict__ w1a,
                        const float* __restrict__ b1a,
                        const float* __restrict__ w1b, const float* __restrict__ b1b) {
    extern __shared__ float sm[];
    float* sw1a = sm;                  // 576  [j][k]
    float* sw1b = sw1a + 576;          // 4096 [j][k]
    float* sba  = sw1b + 4096;
    float* sbb  = sba + 64;
    float* sst  = sbb + 64;            // 4 * 2112

    int tid = threadIdx.x, lane = tid & 31, w = tid >> 5;
    for (int i = tid; i < 576; i += 128) sw1a[i] = w1a[i];
    for (int i = tid; i < 4096; i += 128) sw1b[i] = w1b[i];
    if (tid < HH) { sba[tid] = b1a[tid]; sbb[tid] = b1b[tid]; }
    __syncthreads();

    float* stg = sst + w * 2112;
    int nbase = (blockIdx.x * 4 + w) * 32;

    // stage agg1 (32 nodes x 9) linearly (shared layout == global layout)
    for (int r = 0; r < 9; r++) {
        int idx = r * 32 + lane;
        int gidx = nbase * FIN + idx;
        stg[idx] = (gidx < NN * FIN) ? g_agg1[gidx] : 0.0f;
    }
    __syncwarp();

    float a1[FIN];
#pragma unroll
    for (int k = 0; k < FIN; k++) a1[k] = stg[lane * FIN + k];   // stride 9: conflict-free
    __syncwarp();

    // stage1: 9 -> 64 (uniform scalar weights)
    unsigned long long p1[32];
    float t0 = 0.0f;
#pragma unroll 8
    for (int j = 0; j < HH; j++) {
        float acc = sba[j];
#pragma unroll
        for (int k = 0; k < FIN; k++) acc = fmaf(a1[k], sw1a[j * FIN + k], acc);
        acc = fmaxf(acc, 0.0f);
        if (j & 1) p1[j >> 1] = pk2(t0, acc); else t0 = acc;
    }

    // stage2: 64 -> 64, uniform LDS.64 weights + f32x2
    const unsigned long long* cw = (const unsigned long long*)sw1b;
#pragma unroll 4
    for (int j = 0; j < HH; j++) {
        unsigned long long acc2 = pk2(sbb[j], 0.0f);
#pragma unroll
        for (int q = 0; q < 32; q++) acc2 = ffma2(p1[q], cw[j * 32 + q], acc2);
        float lo, hi; upk2(acc2, lo, hi);
        stg[lane * 66 + j] = fmaxf(lo + hi, 0.0f);
    }
    __syncwarp();

    // coalesced transpose write of h1
    for (int r = 0; r < 64; r++) {
        int idx = r * 32 + lane;
        int gidx = nbase * HH + idx;
        if (gidx < NN * HH) g_h1[gidx] = stg[(r >> 1) * 66 + (r & 1) * 32 + lane];
    }
}

// ================= gather2: warp-per-node (F=64), batched loads =================
__global__ void __launch_bounds__(256) k_gather2(const float* __restrict__ e2w,
                                                 const float* __restrict__ e2b) {
    __shared__ int2 s_edge[8][32];
    int lane = threadIdx.x & 31, w = threadIdx.x >> 5;
    int n = blockIdx.x * 8 + w;
    if (n >= NN) return;

    float2 wv = ((const float2*)e2w)[lane];
    float2 bv = ((const float2*)e2b)[lane];
    const float2* h1f2 = (const float2*)g_h1;

    int base = g_off[n], deg = g_deg[n];
    float2 acc = h1f2[n * 32 + lane];
    for (int c = 0; c < deg; c += 32) {
        int cnt = min(deg - c, 32);
        if (lane < cnt) s_edge[w][lane] = g_csr[base + c + lane];
        __syncwarp();
        if (cnt == 32) {
#pragma unroll
            for (int kb = 0; kb < 4; kb++) {
                float2 h[8]; float a[8];
#pragma unroll
                for (int u = 0; u < 8; u++) {
                    int2 e = s_edge[w][kb * 8 + u];
                    a[u] = __int_as_float(e.y);
                    h[u] = h1f2[e.x * 32 + lane];
                }
#pragma unroll
                for (int u = 0; u < 8; u++) {
                    acc.x += fmaxf(h[u].x + a[u] * wv.x + bv.x, 0.0f);
                    acc.y += fmaxf(h[u].y + a[u] * wv.y + bv.y, 0.0f);
                }
            }
        } else {
            for (int k = 0; k < cnt; k++) {
                int2 e = s_edge[w][k];
                float a = __int_as_float(e.y);
                float2 h = h1f2[e.x * 32 + lane];
                acc.x += fmaxf(h.x + a * wv.x + bv.x, 0.0f);
                acc.y += fmaxf(h.y + a * wv.y + bv.y, 0.0f);
            }
        }
        __syncwarp();
    }
    ((float2*)g_agg2)[n * 32 + lane] = acc;
}

// ================= mlp2 + readout fused: lane=node, uniform shared weights =================
// dynamic smem: swa[4096] | swb[4096] | swr[2048] | sba[64] sbb[64] sbr[32] sw2[32] | stage[4][2112]
#define MLP2_SMEM ((4096 + 4096 + 2048 + 64 + 64 + 32 + 32 + 4 * 2112) * 4)
__global__ void __launch_bounds__(128, 2) k_mlp2ro(const float* __restrict__ w2a,
                        const float* __restrict__ b2a,
                        const float* __restrict__ w2b, const float* __restrict__ b2b,
                        const float* __restrict__ wr1, const float* __restrict__ br1,
                        const float* __restrict__ wr2, const float* __restrict__ br2,
                        const int* __restrict__ batch,
                        const int* __restrict__ tmask,
                        const float* __restrict__ ccost) {
    extern __shared__ float sm[];
    float* swa = sm;                   // 4096 [j][k]
    float* swb = swa + 4096;           // 4096
    float* swr = swb + 4096;           // 2048 [j][k]
    float* sba = swr + 2048;
    float* sbb = sba + 64;
    float* sbr = sbb + 64;
    float* sw2 = sbr + 32;
    float* sst = sw2 + 32;             // 4 * 2112

    int tid = threadIdx.x, lane = tid & 31, w = tid >> 5;
    for (int i = tid; i < 4096; i += 128) { swa[i] = w2a[i]; swb[i] = w2b[i]; }
    for (int i = tid; i < 2048; i += 128) swr[i] = wr1[i];
    if (tid < HH) { sba[tid] = b2a[tid]; sbb[tid] = b2b[tid]; }
    if (tid < 32) { sbr[tid] = br1[tid]; sw2[tid] = wr2[tid]; }
    __syncthreads();

    float* stg = sst + w * 2112;
    int nbase = (blockIdx.x * 4 + w) * 32;

    // stage agg2 (32 nodes x 64) into padded shared (transposed)
    for (int r = 0; r < 64; r++) {
        int idx = r * 32 + lane;
        int gidx = nbase * HH + idx;
        stg[(r >> 1) * 66 + (r & 1) * 32 + lane] = (gidx < NN * HH) ? g_agg2[gidx] : 0.0f;
    }
    __syncwarp();

    unsigned long long p0[32], p1[32], p2[32];
#pragma unroll
    for (int q = 0; q < 32; q++)
        p0[q] = *(const unsigned long long*)&stg[lane * 66 + 2 * q];

    const unsigned long long* cwa = (const unsigned long long*)swa;
    const unsigned long long* cwb = (const unsigned long long*)swb;
    const unsigned long long* cwr = (const unsigned long long*)swr;

    // layer A: 64 -> 64
    float t0 = 0.0f;
#pragma unroll 4
    for (int j = 0; j < HH; j++) {
        unsigned long long acc2 = pk2(sba[j], 0.0f);
#pragma unroll
        for (int q = 0; q < 32; q++) acc2 = ffma2(p0[q], cwa[j * 32 + q], acc2);
        float lo, hi; upk2(acc2, lo, hi);
        float v = fmaxf(lo + hi, 0.0f);
        if (j & 1) p1[j >> 1] = pk2(t0, v); else t0 = v;
    }

    // layer B: 64 -> 64
#pragma unroll 4
    for (int j = 0; j < HH; j++) {
        unsigned long long acc2 = pk2(sbb[j], 0.0f);
#pragma unroll
        for (int q = 0; q < 32; q++) acc2 = ffma2(p1[q], cwb[j * 32 + q], acc2);
        float lo, hi; upk2(acc2, lo, hi);
        float v = fmaxf(lo + hi, 0.0f);
        if (j & 1) p2[j >> 1] = pk2(t0, v); else t0 = v;
    }

    // readout: 64 -> 32 -> 1
    float z = 0.0f;
#pragma unroll 4
    for (int j = 0; j < 32; j++) {
        unsigned long long acc2 = pk2(sbr[j], 0.0f);
#pragma unroll
        for (int q = 0; q < 32; q++) acc2 = ffma2(p2[q], cwr[j * 32 + q], acc2);
        float lo, hi; upk2(acc2, lo, hi);
        z = fmaf(fmaxf(lo + hi, 0.0f), sw2[j], z);
    }

    int n = nbase + lane;
    if (n < NN) {
        z += br2[0];
        float pi = 1.0f / (1.0f + __expf(-z));
        pi *= (1.0f - (float)tmask[n]);
        g_pi[n] = pi;
        atomicAdd(&g_tot[batch[n]], pi * ccost[n]);
    }
}

// ---------------- final ----------------
__global__ void k_final(const int* __restrict__ batch,
                        const float* __restrict__ Bt,
                        float* __restrict__ out) {
    int i = blockIdx.x * blockDim.x + threadIdx.x;
    if (i >= NN) return;
    int b = batch[i];
    float ratio = fminf(Bt[b] / (g_tot[b] + 1e-12f), 1.0f);
    out[i] = g_pi[i] * ratio;
}

extern "C" void kernel_launch(void* const* d_in, const int* in_sizes, int n_in,
                              void* d_out, int out_size) {
    const float* x      = (const float*)d_in[0];
    const int*   ei     = (const int*)d_in[1];
    const float* ea     = (const float*)d_in[2];
    const int*   batch  = (const int*)d_in[3];
    const float* Btot   = (const float*)d_in[4];
    const int*   tmask  = (const int*)d_in[5];
    const float* ccost  = (const float*)d_in[6];
    const float* e1w    = (const float*)d_in[7];
    const float* e1b    = (const float*)d_in[8];
    const float* w1a    = (const float*)d_in[9];
    const float* b1a    = (const float*)d_in[10];
    const float* w1b    = (const float*)d_in[11];
    const float* b1b    = (const float*)d_in[12];
    const float* e2w    = (const float*)d_in[13];
    const float* e2b    = (const float*)d_in[14];
    const float* w2a    = (const float*)d_in[15];
    const float* b2a    = (const float*)d_in[16];
    const float* w2b    = (const float*)d_in[17];
    const float* b2b    = (const float*)d_in[18];
    const float* wr1    = (const float*)d_in[19];
    const float* br1    = (const float*)d_in[20];
    const float* wr2    = (const float*)d_in[21];
    const float* br2    = (const float*)d_in[22];
    float* out = (float*)d_out;

    cudaFuncSetAttribute(k_mlp1,   cudaFuncAttributeMaxDynamicSharedMemorySize, MLP1_SMEM);
    cudaFuncSetAttribute(k_mlp2ro, cudaFuncAttributeMaxDynamicSharedMemorySize, MLP2_SMEM);

    k_init<<<(NN + 255) / 256, 256>>>();
    k_hist<<<(EE + 255) / 256, 256>>>(ei);
    k_scan1<<<NBLK_SCAN, 1024>>>();
    k_scan23<<<(NN + 255) / 256, 256>>>();
    k_scatter<<<(EE + 255) / 256, 256>>>(ei, ea);
    k_gather1<<<(NN + 7) / 8, 256>>>(x, e1w, e1b);
    k_mlp1<<<(NN + 127) / 128, 128, MLP1_SMEM>>>(w1a, b1a, w1b, b1b);
    k_gather2<<<(NN + 7) / 8, 256>>>(e2w, e2b);
    k_mlp2ro<<<(NN + 127) / 128, 128, MLP2_SMEM>>>(w2a, b2a, w2b, b2b,
                                                   wr1, br1, wr2, br2,
                                                   batch, tmask, ccost);
    k_final<<<(NN + 255) / 256, 256>>>(batch, Btot, out);
}